// round 15
// baseline (speedup 1.0000x reference)
#include <cuda_runtime.h>
#include <cuda_fp16.h>
#include <cstdint>

#define B_SZ 16
#define N_SZ 2048
#define HID  128

// static scratch (no allocation allowed)
__device__ __half g_adjh[(size_t)B_SZ * N_SZ * N_SZ];   // 128 MB fp16 adjacency
__device__ __half g_xh[(size_t)B_SZ * N_SZ * HID];      //   8 MB fp16 x
__device__ __half g_p[(size_t)B_SZ * N_SZ * HID];       //   8 MB fp16 projected feats
__device__ __half g_hh[(size_t)B_SZ * N_SZ * HID];      //   8 MB fp16 intermediate h
__device__ __half g_wh[3 * HID * HID];                  //  96 KB fp16 weights

// ---------------------------------------------------------------------------
__device__ __forceinline__ void cp_async16(void* smem, const void* gmem) {
    unsigned s = (unsigned)__cvta_generic_to_shared(smem);
    asm volatile("cp.async.cg.shared.global [%0], [%1], 16;\n" :: "r"(s), "l"(gmem));
}
__device__ __forceinline__ void cp_commit() {
    asm volatile("cp.async.commit_group;\n");
}
template<int N> __device__ __forceinline__ void cp_wait() {
    asm volatile("cp.async.wait_group %0;\n" :: "n"(N));
}
__device__ __forceinline__ unsigned sptr(const void* p) {
    return (unsigned)__cvta_generic_to_shared(p);
}
__device__ __forceinline__ void ldsm4(unsigned* r, unsigned addr) {
    asm volatile("ldmatrix.sync.aligned.m8n8.x4.shared.b16 {%0,%1,%2,%3}, [%4];"
                 : "=r"(r[0]), "=r"(r[1]), "=r"(r[2]), "=r"(r[3]) : "r"(addr));
}
__device__ __forceinline__ void ldsm4t(unsigned* r, unsigned addr) {
    asm volatile("ldmatrix.sync.aligned.m8n8.x4.trans.shared.b16 {%0,%1,%2,%3}, [%4];"
                 : "=r"(r[0]), "=r"(r[1]), "=r"(r[2]), "=r"(r[3]) : "r"(addr));
}
__device__ __forceinline__ void mma16816(float* d, const unsigned* a, const unsigned* b) {
    asm volatile("mma.sync.aligned.m16n8k16.row.col.f32.f16.f16.f32 "
                 "{%0,%1,%2,%3}, {%4,%5,%6,%7}, {%8,%9}, {%0,%1,%2,%3};"
                 : "+f"(d[0]), "+f"(d[1]), "+f"(d[2]), "+f"(d[3])
                 : "r"(a[0]), "r"(a[1]), "r"(a[2]), "r"(a[3]),
                   "r"(b[0]), "r"(b[1]));
}

#define B_LDH  136   // halfs per B smem row (128 + 8 pad); also pw A/B ld

// Warp-tile (32x64) MMA over nks k16-chunks. acc[mi][nj][4].
// ALL fragments load before any MMA issues (wmma-style schedule).
template<int A_LD, int NKS>
__device__ __forceinline__ void mma_steps(float acc[2][8][4],
                                          unsigned aBase, unsigned bBase,
                                          int wr, int wc, int lane)
{
    const int rowSel = lane & 15;
    const int blkSel = lane >> 4;
    #pragma unroll
    for (int ks = 0; ks < NKS; ++ks) {
        unsigned a[2][4];
        unsigned bf[4][4];
        #pragma unroll
        for (int mi = 0; mi < 2; ++mi) {
            unsigned off = ((32 * wr + 16 * mi + rowSel) * A_LD + 16 * ks + 8 * blkSel) * 2;
            ldsm4(a[mi], aBase + off);
        }
        #pragma unroll
        for (int jj = 0; jj < 4; ++jj) {
            unsigned off = ((16 * ks + rowSel) * B_LDH + 64 * wc + 16 * jj + 8 * blkSel) * 2;
            ldsm4t(bf[jj], bBase + off);
        }
        #pragma unroll
        for (int jj = 0; jj < 4; ++jj)
            #pragma unroll
            for (int mi = 0; mi < 2; ++mi) {
                mma16816(acc[mi][2 * jj],     a[mi], bf[jj]);
                mma16816(acc[mi][2 * jj + 1], a[mi], bf[jj] + 2);
            }
    }
}

// LayerNorm epilogue from register accumulators. Needs 3KB free smem at base.
template<typename OutT>
__device__ __forceinline__ void ln_epilogue(float acc[2][8][4], char* smem,
                                            const float* __restrict__ bias,
                                            const float* __restrict__ gamma,
                                            const float* __restrict__ beta,
                                            OutT* __restrict__ ob,
                                            int wr, int wc, int lane, int tid)
{
    float* sS  = (float*)smem;          // [2][128]
    float* sS2 = sS + 256;              // [2][128]
    float* sMu = sS + 512;              // [128]
    float* sRs = sS + 640;              // [128]

    const int g = lane >> 2, q = lane & 3;

    float s[4]  = {0.f, 0.f, 0.f, 0.f};   // idx = mi*2 + h
    float s2[4] = {0.f, 0.f, 0.f, 0.f};
    #pragma unroll
    for (int mi = 0; mi < 2; ++mi)
        #pragma unroll
        for (int nj = 0; nj < 8; ++nj) {
            int C = 64 * wc + 8 * nj + 2 * q;
            float b0 = __ldg(&bias[C]), b1 = __ldg(&bias[C + 1]);
            acc[mi][nj][0] += b0; acc[mi][nj][1] += b1;
            acc[mi][nj][2] += b0; acc[mi][nj][3] += b1;
            #pragma unroll
            for (int h = 0; h < 2; ++h) {
                float v0 = acc[mi][nj][2 * h], v1 = acc[mi][nj][2 * h + 1];
                s[mi * 2 + h]  += v0 + v1;
                s2[mi * 2 + h] += v0 * v0 + v1 * v1;
            }
        }
    #pragma unroll
    for (int i = 0; i < 4; ++i) {
        s[i]  += __shfl_xor_sync(0xFFFFFFFF, s[i], 1);
        s[i]  += __shfl_xor_sync(0xFFFFFFFF, s[i], 2);
        s2[i] += __shfl_xor_sync(0xFFFFFFFF, s2[i], 1);
        s2[i] += __shfl_xor_sync(0xFFFFFFFF, s2[i], 2);
    }
    if (q == 0) {
        #pragma unroll
        for (int mi = 0; mi < 2; ++mi)
            #pragma unroll
            for (int h = 0; h < 2; ++h) {
                int R = 32 * wr + 16 * mi + 8 * h + g;
                sS[wc * 128 + R]  = s[mi * 2 + h];
                sS2[wc * 128 + R] = s2[mi * 2 + h];
            }
    }
    __syncthreads();
    if (tid < 128) {
        float ts  = sS[tid] + sS[128 + tid];
        float ts2 = sS2[tid] + sS2[128 + tid];
        float mu  = ts * (1.f / 128.f);
        float var = ts2 * (1.f / 128.f) - mu * mu;
        sMu[tid] = mu;
        sRs[tid] = rsqrtf(var + 1e-5f);
    }
    __syncthreads();

    #pragma unroll
    for (int mi = 0; mi < 2; ++mi)
        #pragma unroll
        for (int h = 0; h < 2; ++h) {
            int R = 32 * wr + 16 * mi + 8 * h + g;
            float mu = sMu[R], rs = sRs[R];
            #pragma unroll
            for (int nj = 0; nj < 8; ++nj) {
                int C = 64 * wc + 8 * nj + 2 * q;
                float v0 = fmaxf((acc[mi][nj][2 * h] - mu) * rs * __ldg(&gamma[C]) + __ldg(&beta[C]), 0.f);
                float v1 = fmaxf((acc[mi][nj][2 * h + 1] - mu) * rs * __ldg(&gamma[C + 1]) + __ldg(&beta[C + 1]), 0.f);
                if constexpr (sizeof(OutT) == 2)
                    *(__half2*)((__half*)ob + (size_t)R * HID + C) = __floats2half2_rn(v0, v1);
                else
                    *(float2*)((float*)ob + (size_t)R * HID + C) = make_float2(v0, v1);
            }
        }
}

// ---------------------------------------------------------------------------
// conv: fp32 -> fp16, vectorized (x only; adjacency handled inside agg_conv)
// ---------------------------------------------------------------------------
__global__ __launch_bounds__(256) void conv_fp16(const float4* __restrict__ in,
                                                 __half2* __restrict__ out,
                                                 int n4)
{
    int i = blockIdx.x * blockDim.x + threadIdx.x;
    int stride = gridDim.x * blockDim.x;
    for (; i < n4; i += stride) {
        float4 v = in[i];
        out[2 * i + 0] = __floats2half2_rn(v.x, v.y);
        out[2 * i + 1] = __floats2half2_rn(v.z, v.w);
    }
}

__global__ __launch_bounds__(256) void conv_w(const float* __restrict__ W0,
                                              const float* __restrict__ W1,
                                              const float* __restrict__ W2,
                                              __half* __restrict__ out)
{
    int i = blockIdx.x * blockDim.x + threadIdx.x;           // 0 .. 3*16384-1
    const float* src = (i < 16384) ? W0 : (i < 32768) ? W1 : W2;
    int off = i & 16383;
    out[i] = __float2half_rn(src[off]);
}

// ---------------------------------------------------------------------------
// pw_half: p[r, :] = fp16( src[r, :] @ W )   manual m16n8k16, K=128
// ---------------------------------------------------------------------------
#define PW_LD   136
#define PW_SMEM (2 * 128 * PW_LD * 2)       // 69632 B

__global__ __launch_bounds__(256, 2) void pw_half(const __half* __restrict__ src,
                                                  const __half* __restrict__ W,
                                                  __half* __restrict__ out)
{
    extern __shared__ char smraw[];
    __half* sA = (__half*)smraw;
    __half* sB = sA + 128 * PW_LD;

    const int tid  = threadIdx.x;
    const int warp = tid >> 5;
    const int lane = tid & 31;
    const int wr   = warp >> 1;
    const int wc   = warp & 1;
    const size_t row0 = (size_t)blockIdx.x * 128;

    #pragma unroll
    for (int it = 0; it < 8; ++it) {
        int i = tid + it * 256;
        int r = i >> 4, c = i & 15;
        cp_async16(sA + r * PW_LD + c * 8, src + (row0 + r) * HID + c * 8);
    }
    #pragma unroll
    for (int it = 0; it < 8; ++it) {
        int i = tid + it * 256;
        int r = i >> 4, c = i & 15;
        cp_async16(sB + r * PW_LD + c * 8, W + r * HID + c * 8);
    }
    cp_commit();
    cp_wait<0>();
    __syncthreads();

    float acc[2][8][4] = {};
    mma_steps<PW_LD, 8>(acc, sptr(sA), sptr(sB), wr, wc, lane);

    // store epilogue straight from registers (no LN for pw)
    const int g = lane >> 2, q = lane & 3;
    __half* ob = out + row0 * HID;
    #pragma unroll
    for (int mi = 0; mi < 2; ++mi)
        #pragma unroll
        for (int h = 0; h < 2; ++h) {
            int R = 32 * wr + 16 * mi + 8 * h + g;
            #pragma unroll
            for (int nj = 0; nj < 8; ++nj) {
                int C = 64 * wc + 8 * nj + 2 * q;
                *(__half2*)(ob + (size_t)R * HID + C) =
                    __floats2half2_rn(acc[mi][nj][2 * h], acc[mi][nj][2 * h + 1]);
            }
        }
}

// ---------------------------------------------------------------------------
// agg_half (layers 1,2): C = adjh @ p, manual mma, KC=64, 3-stage cp.async,
// fused +bias / LN / ReLU register epilogue.
// ---------------------------------------------------------------------------
#define KC     64
#define A_LDH  72
#define A_STGB (128 * A_LDH * 2)            // 18432 B
#define B_STGB (KC * B_LDH * 2)             // 17408 B
#define OFF_B  (3 * A_STGB)                 // 55296
#define AGG_SMEM (OFF_B + 3 * B_STGB)       // 107520 B

__device__ __forceinline__ void agg_load_stage(char* smem, int stg,
                                               const __half* __restrict__ adjb,
                                               const __half* __restrict__ pb,
                                               int k0, int tid)
{
    char* sA = smem + stg * A_STGB;
    char* sB = smem + OFF_B + stg * B_STGB;
    #pragma unroll
    for (int it = 0; it < 4; ++it) {
        int i = tid + it * 256;
        int r = i >> 3, c = i & 7;
        cp_async16(sA + (r * A_LDH + c * 8) * 2,
                   adjb + (size_t)r * N_SZ + k0 + c * 8);
    }
    #pragma unroll
    for (int it = 0; it < 4; ++it) {
        int i = tid + it * 256;
        int r = i >> 4, c = i & 15;
        cp_async16(sB + (r * B_LDH + c * 8) * 2,
                   pb + (size_t)(k0 + r) * HID + c * 8);
    }
    cp_commit();
}

template<typename OutT>
__global__ __launch_bounds__(256, 2) void agg_half(const __half* __restrict__ adjh,
                                                   const __half* __restrict__ p,
                                                   const float* __restrict__ bias,
                                                   const float* __restrict__ gamma,
                                                   const float* __restrict__ beta,
                                                   OutT* __restrict__ out)
{
    extern __shared__ char smem[];

    const int tid  = threadIdx.x;
    const int warp = tid >> 5;
    const int lane = tid & 31;
    const int wr   = warp >> 1;
    const int wc   = warp & 1;
    const int b    = blockIdx.y;
    const int n0   = blockIdx.x * 128;

    const __half* adjb = adjh + ((size_t)b * N_SZ + n0) * N_SZ;
    const __half* pb   = p + (size_t)b * N_SZ * HID;

    float acc[2][8][4] = {};

    agg_load_stage(smem, 0, adjb, pb, 0, tid);
    agg_load_stage(smem, 1, adjb, pb, KC, tid);

    const unsigned smemBase = sptr(smem);
    const int NT = N_SZ / KC;   // 32
    for (int kt = 0; kt < NT; ++kt) {
        cp_wait<1>();
        __syncthreads();

        int nk = kt + 2;
        if (nk < NT) agg_load_stage(smem, nk % 3, adjb, pb, nk * KC, tid);
        else         cp_commit();

        const int stg = kt % 3;
        mma_steps<A_LDH, KC / 16>(acc,
                                  smemBase + stg * A_STGB,
                                  smemBase + OFF_B + stg * B_STGB,
                                  wr, wc, lane);
    }
    __syncthreads();   // stage reads done; smem reusable for LN stats

    OutT* ob = out + ((size_t)b * N_SZ + n0) * HID;
    ln_epilogue<OutT>(acc, smem, bias, gamma, beta, ob, wr, wc, lane, tid);
}

// ---------------------------------------------------------------------------
// agg_conv (layer 0): fp32 adj loaded via LDG register prefetch (distance 1),
// converted in registers -> STS fp16 A16 (3 buffers) + coalesced STG to
// g_adjh. B via cp.async (4 stages). MMA lags convert by one k-chunk so
// convert and MMA share a single __syncthreads per iteration.
// Register LN epilogue.
// ---------------------------------------------------------------------------
#define CKC       32
#define CV_A16LD  40                          // halfs per fp16 A row (32+8)
#define CV_A16B   (128 * CV_A16LD * 2)        // 10240 B
#define CV_BSTG   (CKC * B_LDH * 2)           // 8704 B
#define CV_OFF_B  (3 * CV_A16B)               // 30720
#define CONV_SMEM (CV_OFF_B + 4 * CV_BSTG)    // 65536 B

__device__ __forceinline__ void conv_loadB(char* smem, int stg,
                                           const __half* __restrict__ pb,
                                           int k0, int tid)
{
    char* sB = smem + CV_OFF_B + stg * CV_BSTG;
    #pragma unroll
    for (int it = 0; it < 2; ++it) {          // 512 chunks: 32 rows x 16
        int i = tid + it * 256;
        int r = i >> 4, c = i & 15;
        cp_async16(sB + (r * B_LDH + c * 8) * 2,
                   pb + (size_t)(k0 + r) * HID + c * 8);
    }
    cp_commit();
}

// prefetch one 128x32 fp32 tile into registers: 4 float4 per thread
// thread layout: i = tid + it*256; r = i>>3 (row), c = i&7 (4-float group)
__device__ __forceinline__ void conv_ldgA(float4 pre[4],
                                          const float* __restrict__ adjb,
                                          int k0, int tid)
{
    #pragma unroll
    for (int it = 0; it < 4; ++it) {
        int i = tid + it * 256;
        int r = i >> 3, c = i & 7;
        pre[it] = *(const float4*)(adjb + (size_t)r * N_SZ + k0 + c * 4);
    }
}

// convert prefetched registers -> fp16 smem buffer + fp16 gmem (adjh)
__device__ __forceinline__ void conv_cvtA(const float4 pre[4], __half* a16,
                                          __half* __restrict__ adjhb,
                                          int k0, int tid)
{
    #pragma unroll
    for (int it = 0; it < 4; ++it) {
        int i = tid + it * 256;
        int r = i >> 3, c = i & 7;
        union { __half2 h[2]; uint2 u; } pk;
        pk.h[0] = __floats2half2_rn(pre[it].x, pre[it].y);
        pk.h[1] = __floats2half2_rn(pre[it].z, pre[it].w);
        *(uint2*)(a16 + r * CV_A16LD + c * 4) = pk.u;
        *(uint2*)(adjhb + (size_t)r * N_SZ + k0 + c * 4) = pk.u;
    }
}

__global__ __launch_bounds__(256, 2) void agg_conv(const float* __restrict__ adj,
                                                   const __half* __restrict__ p,
                                                   const float* __restrict__ bias,
                                                   const float* __restrict__ gamma,
                                                   const float* __restrict__ beta,
                                                   __half* __restrict__ adjh_out,
                                                   __half* __restrict__ out)
{
    extern __shared__ char smem[];

    const int tid  = threadIdx.x;
    const int warp = tid >> 5;
    const int lane = tid & 31;
    const int wr   = warp >> 1;
    const int wc   = warp & 1;
    const int b    = blockIdx.y;
    const int n0   = blockIdx.x * 128;

    const float*  adjb  = adj + ((size_t)b * N_SZ + n0) * N_SZ;
    __half*       adjhb = adjh_out + ((size_t)b * N_SZ + n0) * N_SZ;
    const __half* pb    = p + (size_t)b * N_SZ * HID;

    float acc[2][8][4] = {};
    float4 pre[4];

    // prologue: two B stages in flight + first A tile prefetched
    conv_loadB(smem, 0, pb, 0, tid);
    conv_loadB(smem, 1, pb, CKC, tid);
    conv_ldgA(pre, adjb, 0, tid);

    const unsigned smemBase = sptr(smem);
    const int NT = N_SZ / CKC;   // 64
    for (int kt = 0; kt < NT; ++kt) {
        cp_wait<1>();             // B[kt] landed (B[kt+1] may be in flight)

        // convert prefetched fp32 (k-chunk kt) -> A16[kt%3] + fp16 adjacency
        {
            __half* a16 = (__half*)(smem + (kt % 3) * CV_A16B);
            conv_cvtA(pre, a16, adjhb, kt * CKC, tid);
        }

        // prefetch next A tile (consumed next iteration — full iteration gap)
        if (kt + 1 < NT) conv_ldgA(pre, adjb, (kt + 1) * CKC, tid);

        int nk = kt + 2;
        if (nk < NT) conv_loadB(smem, nk % 4, pb, nk * CKC, tid);
        else         cp_commit();

        __syncthreads();          // A16[kt%3] visible; all threads passed cp_wait

        // MMA lags by one k-chunk: consumes A16[(kt-1)%3] x B[(kt-1)%4]
        if (kt > 0) {
            mma_steps<CV_A16LD, CKC / 16>(acc,
                smemBase + ((kt - 1) % 3) * CV_A16B,
                smemBase + CV_OFF_B + ((kt - 1) & 3) * CV_BSTG,
                wr, wc, lane);
        }
    }

    // tail: final k-chunk's MMA (its STS was made visible by the last sync)
    mma_steps<CV_A16LD, CKC / 16>(acc,
        smemBase + ((NT - 1) % 3) * CV_A16B,
        smemBase + CV_OFF_B + ((NT - 1) & 3) * CV_BSTG,
        wr, wc, lane);
    __syncthreads();   // all reads done; smem reusable for LN stats

    __half* ob = out + ((size_t)b * N_SZ + n0) * HID;
    ln_epilogue<__half>(acc, smem, bias, gamma, beta, ob, wr, wc, lane, tid);
}

// ---------------------------------------------------------------------------
extern "C" void kernel_launch(void* const* d_in, const int* in_sizes, int n_in,
                              void* d_out, int out_size)
{
    const float* x   = (const float*)d_in[0];
    const float* adj = (const float*)d_in[1];
    const float* W[3]  = {(const float*)d_in[2],  (const float*)d_in[6],  (const float*)d_in[10]};
    const float* bb[3] = {(const float*)d_in[3],  (const float*)d_in[7],  (const float*)d_in[11]};
    const float* gg[3] = {(const float*)d_in[4],  (const float*)d_in[8],  (const float*)d_in[12]};
    const float* be[3] = {(const float*)d_in[5],  (const float*)d_in[9],  (const float*)d_in[13]};
    float* out = (float*)d_out;

    cudaFuncSetAttribute(pw_half, cudaFuncAttributeMaxDynamicSharedMemorySize, PW_SMEM);
    cudaFuncSetAttribute(agg_half<__half>, cudaFuncAttributeMaxDynamicSharedMemorySize, AGG_SMEM);
    cudaFuncSetAttribute(agg_half<float>,  cudaFuncAttributeMaxDynamicSharedMemorySize, AGG_SMEM);
    cudaFuncSetAttribute(agg_conv, cudaFuncAttributeMaxDynamicSharedMemorySize, CONV_SMEM);

    __half *adjh, *xh, *pp, *hh, *wh;
    cudaGetSymbolAddress((void**)&adjh, g_adjh);
    cudaGetSymbolAddress((void**)&xh,   g_xh);
    cudaGetSymbolAddress((void**)&pp,   g_p);
    cudaGetSymbolAddress((void**)&hh,   g_hh);
    cudaGetSymbolAddress((void**)&wh,   g_wh);

    conv_fp16<<<1024, 256>>>((const float4*)x, (__half2*)xh, (B_SZ * N_SZ * HID) / 4);
    conv_w<<<192, 256>>>(W[0], W[1], W[2], wh);

    dim3 aggGrid(N_SZ / 128, B_SZ);   // (16, 16)

    // layer 0: projection then fused convert+agg (also emits fp16 adjacency)
    pw_half<<<(B_SZ * N_SZ) / 128, 256, PW_SMEM>>>(xh, wh, pp);
    agg_conv<<<aggGrid, 256, CONV_SMEM>>>(adj, pp, bb[0], gg[0], be[0], adjh, hh);
    // layer 1
    pw_half<<<(B_SZ * N_SZ) / 128, 256, PW_SMEM>>>(hh, wh + 1 * HID * HID, pp);
    agg_half<__half><<<aggGrid, 256, AGG_SMEM>>>(adjh, pp, bb[1], gg[1], be[1], hh);
    // layer 2
    pw_half<<<(B_SZ * N_SZ) / 128, 256, PW_SMEM>>>(hh, wh + 2 * HID * HID, pp);
    agg_half<float><<<aggGrid, 256, AGG_SMEM>>>(adjh, pp, bb[2], gg[2], be[2], out);
}

// round 16
// speedup vs baseline: 1.0054x; 1.0054x over previous
#include <cuda_runtime.h>
#include <cuda_fp16.h>
#include <cstdint>

#define B_SZ 16
#define N_SZ 2048
#define HID  128

// static scratch (no allocation allowed)
__device__ __half g_adjh[(size_t)B_SZ * N_SZ * N_SZ];   // 128 MB fp16 adjacency
__device__ __half g_xh[(size_t)B_SZ * N_SZ * HID];      //   8 MB fp16 x
__device__ __half g_p[(size_t)B_SZ * N_SZ * HID];       //   8 MB fp16 projected feats
__device__ __half g_hh[(size_t)B_SZ * N_SZ * HID];      //   8 MB fp16 intermediate h
__device__ __half g_wh[3 * HID * HID];                  //  96 KB fp16 weights

// ---------------------------------------------------------------------------
__device__ __forceinline__ void cp_async16(void* smem, const void* gmem) {
    unsigned s = (unsigned)__cvta_generic_to_shared(smem);
    asm volatile("cp.async.cg.shared.global [%0], [%1], 16;\n" :: "r"(s), "l"(gmem));
}
__device__ __forceinline__ void cp_commit() {
    asm volatile("cp.async.commit_group;\n");
}
template<int N> __device__ __forceinline__ void cp_wait() {
    asm volatile("cp.async.wait_group %0;\n" :: "n"(N));
}
__device__ __forceinline__ unsigned sptr(const void* p) {
    return (unsigned)__cvta_generic_to_shared(p);
}
__device__ __forceinline__ void ldsm4(unsigned* r, unsigned addr) {
    asm volatile("ldmatrix.sync.aligned.m8n8.x4.shared.b16 {%0,%1,%2,%3}, [%4];"
                 : "=r"(r[0]), "=r"(r[1]), "=r"(r[2]), "=r"(r[3]) : "r"(addr));
}
__device__ __forceinline__ void ldsm4t(unsigned* r, unsigned addr) {
    asm volatile("ldmatrix.sync.aligned.m8n8.x4.trans.shared.b16 {%0,%1,%2,%3}, [%4];"
                 : "=r"(r[0]), "=r"(r[1]), "=r"(r[2]), "=r"(r[3]) : "r"(addr));
}
__device__ __forceinline__ void mma16816(float* d, const unsigned* a, const unsigned* b) {
    asm volatile("mma.sync.aligned.m16n8k16.row.col.f32.f16.f16.f32 "
                 "{%0,%1,%2,%3}, {%4,%5,%6,%7}, {%8,%9}, {%0,%1,%2,%3};"
                 : "+f"(d[0]), "+f"(d[1]), "+f"(d[2]), "+f"(d[3])
                 : "r"(a[0]), "r"(a[1]), "r"(a[2]), "r"(a[3]),
                   "r"(b[0]), "r"(b[1]));
}

#define B_LDH  136   // halfs per B smem row (128 + 8 pad); also pw A/B ld

// Warp-tile (32x64) MMA over nks k16-chunks. acc[mi][nj][4].
// ALL fragments load before any MMA issues (wmma-style schedule).
template<int A_LD, int NKS>
__device__ __forceinline__ void mma_steps(float acc[2][8][4],
                                          unsigned aBase, unsigned bBase,
                                          int wr, int wc, int lane)
{
    const int rowSel = lane & 15;
    const int blkSel = lane >> 4;
    #pragma unroll
    for (int ks = 0; ks < NKS; ++ks) {
        unsigned a[2][4];
        unsigned bf[4][4];
        #pragma unroll
        for (int mi = 0; mi < 2; ++mi) {
            unsigned off = ((32 * wr + 16 * mi + rowSel) * A_LD + 16 * ks + 8 * blkSel) * 2;
            ldsm4(a[mi], aBase + off);
        }
        #pragma unroll
        for (int jj = 0; jj < 4; ++jj) {
            unsigned off = ((16 * ks + rowSel) * B_LDH + 64 * wc + 16 * jj + 8 * blkSel) * 2;
            ldsm4t(bf[jj], bBase + off);
        }
        #pragma unroll
        for (int jj = 0; jj < 4; ++jj)
            #pragma unroll
            for (int mi = 0; mi < 2; ++mi) {
                mma16816(acc[mi][2 * jj],     a[mi], bf[jj]);
                mma16816(acc[mi][2 * jj + 1], a[mi], bf[jj] + 2);
            }
    }
}

// LayerNorm epilogue from register accumulators. Needs 3KB free smem at base.
template<typename OutT>
__device__ __forceinline__ void ln_epilogue(float acc[2][8][4], char* smem,
                                            const float* __restrict__ bias,
                                            const float* __restrict__ gamma,
                                            const float* __restrict__ beta,
                                            OutT* __restrict__ ob,
                                            int wr, int wc, int lane, int tid)
{
    float* sS  = (float*)smem;          // [2][128]
    float* sS2 = sS + 256;              // [2][128]
    float* sMu = sS + 512;              // [128]
    float* sRs = sS + 640;              // [128]

    const int g = lane >> 2, q = lane & 3;

    float s[4]  = {0.f, 0.f, 0.f, 0.f};   // idx = mi*2 + h
    float s2[4] = {0.f, 0.f, 0.f, 0.f};
    #pragma unroll
    for (int mi = 0; mi < 2; ++mi)
        #pragma unroll
        for (int nj = 0; nj < 8; ++nj) {
            int C = 64 * wc + 8 * nj + 2 * q;
            float b0 = __ldg(&bias[C]), b1 = __ldg(&bias[C + 1]);
            acc[mi][nj][0] += b0; acc[mi][nj][1] += b1;
            acc[mi][nj][2] += b0; acc[mi][nj][3] += b1;
            #pragma unroll
            for (int h = 0; h < 2; ++h) {
                float v0 = acc[mi][nj][2 * h], v1 = acc[mi][nj][2 * h + 1];
                s[mi * 2 + h]  += v0 + v1;
                s2[mi * 2 + h] += v0 * v0 + v1 * v1;
            }
        }
    #pragma unroll
    for (int i = 0; i < 4; ++i) {
        s[i]  += __shfl_xor_sync(0xFFFFFFFF, s[i], 1);
        s[i]  += __shfl_xor_sync(0xFFFFFFFF, s[i], 2);
        s2[i] += __shfl_xor_sync(0xFFFFFFFF, s2[i], 1);
        s2[i] += __shfl_xor_sync(0xFFFFFFFF, s2[i], 2);
    }
    if (q == 0) {
        #pragma unroll
        for (int mi = 0; mi < 2; ++mi)
            #pragma unroll
            for (int h = 0; h < 2; ++h) {
                int R = 32 * wr + 16 * mi + 8 * h + g;
                sS[wc * 128 + R]  = s[mi * 2 + h];
                sS2[wc * 128 + R] = s2[mi * 2 + h];
            }
    }
    __syncthreads();
    if (tid < 128) {
        float ts  = sS[tid] + sS[128 + tid];
        float ts2 = sS2[tid] + sS2[128 + tid];
        float mu  = ts * (1.f / 128.f);
        float var = ts2 * (1.f / 128.f) - mu * mu;
        sMu[tid] = mu;
        sRs[tid] = rsqrtf(var + 1e-5f);
    }
    __syncthreads();

    #pragma unroll
    for (int mi = 0; mi < 2; ++mi)
        #pragma unroll
        for (int h = 0; h < 2; ++h) {
            int R = 32 * wr + 16 * mi + 8 * h + g;
            float mu = sMu[R], rs = sRs[R];
            #pragma unroll
            for (int nj = 0; nj < 8; ++nj) {
                int C = 64 * wc + 8 * nj + 2 * q;
                float v0 = fmaxf((acc[mi][nj][2 * h] - mu) * rs * __ldg(&gamma[C]) + __ldg(&beta[C]), 0.f);
                float v1 = fmaxf((acc[mi][nj][2 * h + 1] - mu) * rs * __ldg(&gamma[C + 1]) + __ldg(&beta[C + 1]), 0.f);
                if constexpr (sizeof(OutT) == 2)
                    *(__half2*)((__half*)ob + (size_t)R * HID + C) = __floats2half2_rn(v0, v1);
                else
                    *(float2*)((float*)ob + (size_t)R * HID + C) = make_float2(v0, v1);
            }
        }
}

// ---------------------------------------------------------------------------
// conv_head: fp32 -> fp16 for x AND the three weight matrices, one launch.
// ---------------------------------------------------------------------------
#define NX4 ((B_SZ * N_SZ * HID) / 4)      // 1048576 float4 of x
#define NW4 ((3 * HID * HID) / 4)          // 12288 float4 of W
__global__ __launch_bounds__(256) void conv_head(const float4* __restrict__ x,
                                                 const float4* __restrict__ W0,
                                                 const float4* __restrict__ W1,
                                                 const float4* __restrict__ W2,
                                                 __half2* __restrict__ xh,
                                                 __half2* __restrict__ wh)
{
    int i = blockIdx.x * blockDim.x + threadIdx.x;
    int stride = gridDim.x * blockDim.x;
    for (; i < NX4 + NW4; i += stride) {
        float4 v;
        __half2* out;
        if (i < NX4) {
            v = x[i];
            out = xh + 2 * (size_t)i;
        } else {
            int j = i - NX4;                       // 0 .. NW4-1, 4096 per W
            const float4* src = (j < 4096) ? W0 : (j < 8192) ? W1 : W2;
            v = src[j & 4095];
            out = wh + 2 * (size_t)j;
        }
        out[0] = __floats2half2_rn(v.x, v.y);
        out[1] = __floats2half2_rn(v.z, v.w);
    }
}

// ---------------------------------------------------------------------------
// pw_half: p[r, :] = fp16( src[r, :] @ W )   manual m16n8k16, K=128.
// 64-row tiles, 512 CTAs, 3 CTAs/SM (forced via launch_bounds) — higher
// occupancy to hide the single-shot cp.async wait.
// ---------------------------------------------------------------------------
#define PW_LD   136
#define PW_A_BYTES (64 * PW_LD * 2)         // 17408
#define PW_SMEM (PW_A_BYTES + 128 * PW_LD * 2)  // 52224 B

__global__ __launch_bounds__(256, 3) void pw_half(const __half* __restrict__ src,
                                                  const __half* __restrict__ W,
                                                  __half* __restrict__ out)
{
    extern __shared__ char smraw[];
    __half* sA = (__half*)smraw;                 // 64 x 136
    __half* sB = (__half*)(smraw + PW_A_BYTES);  // 128 x 136

    const int tid  = threadIdx.x;
    const int warp = tid >> 5;
    const int lane = tid & 31;
    const int wr   = warp >> 1;                  // 0..3 (16-row slice)
    const int wc   = warp & 1;                   // 0..1 (64-col slice)
    const size_t row0 = (size_t)blockIdx.x * 64;

    #pragma unroll
    for (int it = 0; it < 4; ++it) {             // 1024 chunks: 64 rows x 16
        int i = tid + it * 256;
        int r = i >> 4, c = i & 15;
        cp_async16(sA + r * PW_LD + c * 8, src + (row0 + r) * HID + c * 8);
    }
    #pragma unroll
    for (int it = 0; it < 8; ++it) {             // 2048 chunks: 128 rows x 16
        int i = tid + it * 256;
        int r = i >> 4, c = i & 15;
        cp_async16(sB + r * PW_LD + c * 8, W + r * HID + c * 8);
    }
    cp_commit();
    cp_wait<0>();
    __syncthreads();

    const unsigned aBase = sptr(sA);
    const unsigned bBase = sptr(sB);
    const int rowSel = lane & 15;
    const int blkSel = lane >> 4;

    float acc[8][4] = {};                        // warp tile 16x64
    #pragma unroll
    for (int ks = 0; ks < 8; ++ks) {
        unsigned a[4];
        unsigned bf[4][4];
        {
            unsigned off = ((16 * wr + rowSel) * PW_LD + 16 * ks + 8 * blkSel) * 2;
            ldsm4(a, aBase + off);
        }
        #pragma unroll
        for (int jj = 0; jj < 4; ++jj) {
            unsigned off = ((16 * ks + rowSel) * B_LDH + 64 * wc + 16 * jj + 8 * blkSel) * 2;
            ldsm4t(bf[jj], bBase + off);
        }
        #pragma unroll
        for (int jj = 0; jj < 4; ++jj) {
            mma16816(acc[2 * jj],     a, bf[jj]);
            mma16816(acc[2 * jj + 1], a, bf[jj] + 2);
        }
    }

    // store straight from registers
    const int g = lane >> 2, q = lane & 3;
    __half* ob = out + row0 * HID;
    #pragma unroll
    for (int h = 0; h < 2; ++h) {
        int R = 16 * wr + 8 * h + g;
        #pragma unroll
        for (int nj = 0; nj < 8; ++nj) {
            int C = 64 * wc + 8 * nj + 2 * q;
            *(__half2*)(ob + (size_t)R * HID + C) =
                __floats2half2_rn(acc[nj][2 * h], acc[nj][2 * h + 1]);
        }
    }
}

// ---------------------------------------------------------------------------
// agg_half (layers 1,2): C = adjh @ p, manual mma, KC=64, 3-stage cp.async,
// fused +bias / LN / ReLU register epilogue.  (unchanged from R14)
// ---------------------------------------------------------------------------
#define KC     64
#define A_LDH  72
#define A_STGB (128 * A_LDH * 2)            // 18432 B
#define B_STGB (KC * B_LDH * 2)             // 17408 B
#define OFF_B  (3 * A_STGB)                 // 55296
#define AGG_SMEM (OFF_B + 3 * B_STGB)       // 107520 B

__device__ __forceinline__ void agg_load_stage(char* smem, int stg,
                                               const __half* __restrict__ adjb,
                                               const __half* __restrict__ pb,
                                               int k0, int tid)
{
    char* sA = smem + stg * A_STGB;
    char* sB = smem + OFF_B + stg * B_STGB;
    #pragma unroll
    for (int it = 0; it < 4; ++it) {
        int i = tid + it * 256;
        int r = i >> 3, c = i & 7;
        cp_async16(sA + (r * A_LDH + c * 8) * 2,
                   adjb + (size_t)r * N_SZ + k0 + c * 8);
    }
    #pragma unroll
    for (int it = 0; it < 4; ++it) {
        int i = tid + it * 256;
        int r = i >> 4, c = i & 15;
        cp_async16(sB + (r * B_LDH + c * 8) * 2,
                   pb + (size_t)(k0 + r) * HID + c * 8);
    }
    cp_commit();
}

template<typename OutT>
__global__ __launch_bounds__(256, 2) void agg_half(const __half* __restrict__ adjh,
                                                   const __half* __restrict__ p,
                                                   const float* __restrict__ bias,
                                                   const float* __restrict__ gamma,
                                                   const float* __restrict__ beta,
                                                   OutT* __restrict__ out)
{
    extern __shared__ char smem[];

    const int tid  = threadIdx.x;
    const int warp = tid >> 5;
    const int lane = tid & 31;
    const int wr   = warp >> 1;
    const int wc   = warp & 1;
    const int b    = blockIdx.y;
    const int n0   = blockIdx.x * 128;

    const __half* adjb = adjh + ((size_t)b * N_SZ + n0) * N_SZ;
    const __half* pb   = p + (size_t)b * N_SZ * HID;

    float acc[2][8][4] = {};

    agg_load_stage(smem, 0, adjb, pb, 0, tid);
    agg_load_stage(smem, 1, adjb, pb, KC, tid);

    const unsigned smemBase = sptr(smem);
    const int NT = N_SZ / KC;   // 32
    for (int kt = 0; kt < NT; ++kt) {
        cp_wait<1>();
        __syncthreads();

        int nk = kt + 2;
        if (nk < NT) agg_load_stage(smem, nk % 3, adjb, pb, nk * KC, tid);
        else         cp_commit();

        const int stg = kt % 3;
        mma_steps<A_LDH, KC / 16>(acc,
                                  smemBase + stg * A_STGB,
                                  smemBase + OFF_B + stg * B_STGB,
                                  wr, wc, lane);
    }
    __syncthreads();   // stage reads done; smem reusable for LN stats

    OutT* ob = out + ((size_t)b * N_SZ + n0) * HID;
    ln_epilogue<OutT>(acc, smem, bias, gamma, beta, ob, wr, wc, lane, tid);
}

// ---------------------------------------------------------------------------
// agg_conv (layer 0): cp.async fp32 adj staging (3 stages, KC=32), single
// sync per iteration: convert(stage kt -> A16[kt%2], + STG.128 to g_adjh)
// overlaps MMA on A16[(kt-1)%2] x B[(kt-1)%4]. Register LN epilogue.
// (R14 version — the register-prefetch variant of R15 was neutral.)
// ---------------------------------------------------------------------------
#define CKC       32
#define CV_A32LD  36                          // floats per fp32 A row (32+4)
#define CV_A32B   (128 * CV_A32LD * 4)        // 18432 B
#define CV_A16LD  40                          // halfs per fp16 A row (32+8)
#define CV_A16B   (128 * CV_A16LD * 2)        // 10240 B
#define CV_OFF_A16 (3 * CV_A32B)              // 55296
#define CV_BSTG   (CKC * B_LDH * 2)           // 8704 B
#define CV_OFF_B  (CV_OFF_A16 + 2 * CV_A16B)  // 75776
#define CONV_SMEM (CV_OFF_B + 4 * CV_BSTG)    // 110592 B

__device__ __forceinline__ void conv_load_stage(char* smem, int a_stg, int b_stg,
                                                const float* __restrict__ adjb,
                                                const __half* __restrict__ pb,
                                                int k0, int tid)
{
    float* sA = (float*)(smem + a_stg * CV_A32B);
    char*  sB = smem + CV_OFF_B + b_stg * CV_BSTG;
    #pragma unroll
    for (int it = 0; it < 4; ++it) {          // 1024 chunks: 128 rows x 8 float4
        int i = tid + it * 256;
        int r = i >> 3, c = i & 7;
        cp_async16(sA + r * CV_A32LD + c * 4,
                   adjb + (size_t)r * N_SZ + k0 + c * 4);
    }
    #pragma unroll
    for (int it = 0; it < 2; ++it) {          // 512 chunks: 32 rows x 16
        int i = tid + it * 256;
        int r = i >> 4, c = i & 15;
        cp_async16(sB + (r * B_LDH + c * 8) * 2,
                   pb + (size_t)(k0 + r) * HID + c * 8);
    }
    cp_commit();
}

__global__ __launch_bounds__(256, 2) void agg_conv(const float* __restrict__ adj,
                                                   const __half* __restrict__ p,
                                                   const float* __restrict__ bias,
                                                   const float* __restrict__ gamma,
                                                   const float* __restrict__ beta,
                                                   __half* __restrict__ adjh_out,
                                                   __half* __restrict__ out)
{
    extern __shared__ char smem[];

    const int tid  = threadIdx.x;
    const int warp = tid >> 5;
    const int lane = tid & 31;
    const int wr   = warp >> 1;
    const int wc   = warp & 1;
    const int b    = blockIdx.y;
    const int n0   = blockIdx.x * 128;

    const float*  adjb  = adj + ((size_t)b * N_SZ + n0) * N_SZ;
    __half*       adjhb = adjh_out + ((size_t)b * N_SZ + n0) * N_SZ;
    const __half* pb    = p + (size_t)b * N_SZ * HID;

    float acc[2][8][4] = {};

    // prologue: two stages in flight
    conv_load_stage(smem, 0, 0, adjb, pb, 0, tid);
    conv_load_stage(smem, 1, 1, adjb, pb, CKC, tid);

    const unsigned smemBase = sptr(smem);
    const int NT = N_SZ / CKC;   // 64
    for (int kt = 0; kt < NT; ++kt) {
        cp_wait<1>();
        __syncthreads();          // fp32 stage kt + B stage kt ready;
                                  // also: A16[(kt-1)%2] writes visible

        int nk = kt + 2;
        if (nk < NT) conv_load_stage(smem, nk % 3, nk % 4, adjb, pb, nk * CKC, tid);
        else         cp_commit();

        // convert fp32 stage kt -> A16[kt%2] (+ fp16 adjacency to gmem)
        {
            const float* a32 = (const float*)(smem + (kt % 3) * CV_A32B);
            __half* a16 = (__half*)(smem + CV_OFF_A16 + (kt & 1) * CV_A16B);
            const int k0 = kt * CKC;
            #pragma unroll
            for (int it = 0; it < 2; ++it) {   // 512 out-chunks of 16B
                int i = tid + it * 256;
                int r = i >> 2, j = i & 3;     // 128 rows x 4 groups of 8 floats
                float4 v0 = *(const float4*)(a32 + r * CV_A32LD + j * 8);
                float4 v1 = *(const float4*)(a32 + r * CV_A32LD + j * 8 + 4);
                union { __half2 h[4]; uint4 u; } pk;
                pk.h[0] = __floats2half2_rn(v0.x, v0.y);
                pk.h[1] = __floats2half2_rn(v0.z, v0.w);
                pk.h[2] = __floats2half2_rn(v1.x, v1.y);
                pk.h[3] = __floats2half2_rn(v1.z, v1.w);
                *(uint4*)(a16 + r * CV_A16LD + j * 8) = pk.u;
                *(uint4*)(adjhb + (size_t)r * N_SZ + k0 + j * 8) = pk.u;
            }
        }

        // MMA lags by one k-chunk: consumes A16[(kt-1)%2] x B[(kt-1)%4]
        if (kt > 0) {
            mma_steps<CV_A16LD, CKC / 16>(acc,
                smemBase + CV_OFF_A16 + ((kt - 1) & 1) * CV_A16B,
                smemBase + CV_OFF_B + ((kt - 1) & 3) * CV_BSTG,
                wr, wc, lane);
        }
    }

    // tail: final k-chunk's MMA
    __syncthreads();   // last convert visible to all warps
    mma_steps<CV_A16LD, CKC / 16>(acc,
        smemBase + CV_OFF_A16 + ((NT - 1) & 1) * CV_A16B,
        smemBase + CV_OFF_B + ((NT - 1) & 3) * CV_BSTG,
        wr, wc, lane);
    __syncthreads();   // all reads done; smem reusable for LN stats

    __half* ob = out + ((size_t)b * N_SZ + n0) * HID;
    ln_epilogue<__half>(acc, smem, bias, gamma, beta, ob, wr, wc, lane, tid);
}

// ---------------------------------------------------------------------------
extern "C" void kernel_launch(void* const* d_in, const int* in_sizes, int n_in,
                              void* d_out, int out_size)
{
    const float* x   = (const float*)d_in[0];
    const float* adj = (const float*)d_in[1];
    const float* W[3]  = {(const float*)d_in[2],  (const float*)d_in[6],  (const float*)d_in[10]};
    const float* bb[3] = {(const float*)d_in[3],  (const float*)d_in[7],  (const float*)d_in[11]};
    const float* gg[3] = {(const float*)d_in[4],  (const float*)d_in[8],  (const float*)d_in[12]};
    const float* be[3] = {(const float*)d_in[5],  (const float*)d_in[9],  (const float*)d_in[13]};
    float* out = (float*)d_out;

    cudaFuncSetAttribute(pw_half, cudaFuncAttributeMaxDynamicSharedMemorySize, PW_SMEM);
    cudaFuncSetAttribute(agg_half<__half>, cudaFuncAttributeMaxDynamicSharedMemorySize, AGG_SMEM);
    cudaFuncSetAttribute(agg_half<float>,  cudaFuncAttributeMaxDynamicSharedMemorySize, AGG_SMEM);
    cudaFuncSetAttribute(agg_conv, cudaFuncAttributeMaxDynamicSharedMemorySize, CONV_SMEM);

    __half *adjh, *xh, *pp, *hh, *wh;
    cudaGetSymbolAddress((void**)&adjh, g_adjh);
    cudaGetSymbolAddress((void**)&xh,   g_xh);
    cudaGetSymbolAddress((void**)&pp,   g_p);
    cudaGetSymbolAddress((void**)&hh,   g_hh);
    cudaGetSymbolAddress((void**)&wh,   g_wh);

    // one launch: convert x + all three W to fp16
    conv_head<<<1024, 256>>>((const float4*)x,
                             (const float4*)W[0], (const float4*)W[1], (const float4*)W[2],
                             (__half2*)xh, (__half2*)wh);

    dim3 aggGrid(N_SZ / 128, B_SZ);   // (16, 16)
    const int pwGrid = (B_SZ * N_SZ) / 64;   // 512

    // layer 0: projection then fused convert+agg (also emits fp16 adjacency)
    pw_half<<<pwGrid, 256, PW_SMEM>>>(xh, wh, pp);
    agg_conv<<<aggGrid, 256, CONV_SMEM>>>(adj, pp, bb[0], gg[0], be[0], adjh, hh);
    // layer 1
    pw_half<<<pwGrid, 256, PW_SMEM>>>(hh, wh + 1 * HID * HID, pp);
    agg_half<__half><<<aggGrid, 256, AGG_SMEM>>>(adjh, pp, bb[1], gg[1], be[1], hh);
    // layer 2
    pw_half<<<pwGrid, 256, PW_SMEM>>>(hh, wh + 2 * HID * HID, pp);
    agg_half<float><<<aggGrid, 256, AGG_SMEM>>>(adjh, pp, bb[2], gg[2], be[2], out);
}

// round 17
// speedup vs baseline: 1.0203x; 1.0148x over previous
#include <cuda_runtime.h>
#include <cuda_fp16.h>
#include <cstdint>

#define B_SZ 16
#define N_SZ 2048
#define HID  128

// static scratch (no allocation allowed)
__device__ __half g_adjh[(size_t)B_SZ * N_SZ * N_SZ];   // 128 MB fp16 adjacency
__device__ __half g_p[(size_t)B_SZ * N_SZ * HID];       //   8 MB fp16 projected feats
__device__ __half g_hh[(size_t)B_SZ * N_SZ * HID];      //   8 MB fp16 intermediate h
__device__ __half g_wh[3 * HID * HID];                  //  96 KB fp16 weights

// ---------------------------------------------------------------------------
__device__ __forceinline__ void cp_async16(void* smem, const void* gmem) {
    unsigned s = (unsigned)__cvta_generic_to_shared(smem);
    asm volatile("cp.async.cg.shared.global [%0], [%1], 16;\n" :: "r"(s), "l"(gmem));
}
__device__ __forceinline__ void cp_commit() {
    asm volatile("cp.async.commit_group;\n");
}
template<int N> __device__ __forceinline__ void cp_wait() {
    asm volatile("cp.async.wait_group %0;\n" :: "n"(N));
}
__device__ __forceinline__ unsigned sptr(const void* p) {
    return (unsigned)__cvta_generic_to_shared(p);
}
__device__ __forceinline__ void ldsm4(unsigned* r, unsigned addr) {
    asm volatile("ldmatrix.sync.aligned.m8n8.x4.shared.b16 {%0,%1,%2,%3}, [%4];"
                 : "=r"(r[0]), "=r"(r[1]), "=r"(r[2]), "=r"(r[3]) : "r"(addr));
}
__device__ __forceinline__ void ldsm4t(unsigned* r, unsigned addr) {
    asm volatile("ldmatrix.sync.aligned.m8n8.x4.trans.shared.b16 {%0,%1,%2,%3}, [%4];"
                 : "=r"(r[0]), "=r"(r[1]), "=r"(r[2]), "=r"(r[3]) : "r"(addr));
}
__device__ __forceinline__ void mma16816(float* d, const unsigned* a, const unsigned* b) {
    asm volatile("mma.sync.aligned.m16n8k16.row.col.f32.f16.f16.f32 "
                 "{%0,%1,%2,%3}, {%4,%5,%6,%7}, {%8,%9}, {%0,%1,%2,%3};"
                 : "+f"(d[0]), "+f"(d[1]), "+f"(d[2]), "+f"(d[3])
                 : "r"(a[0]), "r"(a[1]), "r"(a[2]), "r"(a[3]),
                   "r"(b[0]), "r"(b[1]));
}

#define B_LDH  136   // halfs per B smem row (128 + 8 pad); also pw A/B ld

// Warp-tile (32x64) MMA over nks k16-chunks. acc[mi][nj][4].
// ALL fragments load before any MMA issues (wmma-style schedule).
template<int A_LD, int NKS>
__device__ __forceinline__ void mma_steps(float acc[2][8][4],
                                          unsigned aBase, unsigned bBase,
                                          int wr, int wc, int lane)
{
    const int rowSel = lane & 15;
    const int blkSel = lane >> 4;
    #pragma unroll
    for (int ks = 0; ks < NKS; ++ks) {
        unsigned a[2][4];
        unsigned bf[4][4];
        #pragma unroll
        for (int mi = 0; mi < 2; ++mi) {
            unsigned off = ((32 * wr + 16 * mi + rowSel) * A_LD + 16 * ks + 8 * blkSel) * 2;
            ldsm4(a[mi], aBase + off);
        }
        #pragma unroll
        for (int jj = 0; jj < 4; ++jj) {
            unsigned off = ((16 * ks + rowSel) * B_LDH + 64 * wc + 16 * jj + 8 * blkSel) * 2;
            ldsm4t(bf[jj], bBase + off);
        }
        #pragma unroll
        for (int jj = 0; jj < 4; ++jj)
            #pragma unroll
            for (int mi = 0; mi < 2; ++mi) {
                mma16816(acc[mi][2 * jj],     a[mi], bf[jj]);
                mma16816(acc[mi][2 * jj + 1], a[mi], bf[jj] + 2);
            }
    }
}

// LayerNorm epilogue from register accumulators. Needs 3KB free smem at base.
template<typename OutT>
__device__ __forceinline__ void ln_epilogue(float acc[2][8][4], char* smem,
                                            const float* __restrict__ bias,
                                            const float* __restrict__ gamma,
                                            const float* __restrict__ beta,
                                            OutT* __restrict__ ob,
                                            int wr, int wc, int lane, int tid)
{
    float* sS  = (float*)smem;          // [2][128]
    float* sS2 = sS + 256;              // [2][128]
    float* sMu = sS + 512;              // [128]
    float* sRs = sS + 640;              // [128]

    const int g = lane >> 2, q = lane & 3;

    float s[4]  = {0.f, 0.f, 0.f, 0.f};   // idx = mi*2 + h
    float s2[4] = {0.f, 0.f, 0.f, 0.f};
    #pragma unroll
    for (int mi = 0; mi < 2; ++mi)
        #pragma unroll
        for (int nj = 0; nj < 8; ++nj) {
            int C = 64 * wc + 8 * nj + 2 * q;
            float b0 = __ldg(&bias[C]), b1 = __ldg(&bias[C + 1]);
            acc[mi][nj][0] += b0; acc[mi][nj][1] += b1;
            acc[mi][nj][2] += b0; acc[mi][nj][3] += b1;
            #pragma unroll
            for (int h = 0; h < 2; ++h) {
                float v0 = acc[mi][nj][2 * h], v1 = acc[mi][nj][2 * h + 1];
                s[mi * 2 + h]  += v0 + v1;
                s2[mi * 2 + h] += v0 * v0 + v1 * v1;
            }
        }
    #pragma unroll
    for (int i = 0; i < 4; ++i) {
        s[i]  += __shfl_xor_sync(0xFFFFFFFF, s[i], 1);
        s[i]  += __shfl_xor_sync(0xFFFFFFFF, s[i], 2);
        s2[i] += __shfl_xor_sync(0xFFFFFFFF, s2[i], 1);
        s2[i] += __shfl_xor_sync(0xFFFFFFFF, s2[i], 2);
    }
    if (q == 0) {
        #pragma unroll
        for (int mi = 0; mi < 2; ++mi)
            #pragma unroll
            for (int h = 0; h < 2; ++h) {
                int R = 32 * wr + 16 * mi + 8 * h + g;
                sS[wc * 128 + R]  = s[mi * 2 + h];
                sS2[wc * 128 + R] = s2[mi * 2 + h];
            }
    }
    __syncthreads();
    if (tid < 128) {
        float ts  = sS[tid] + sS[128 + tid];
        float ts2 = sS2[tid] + sS2[128 + tid];
        float mu  = ts * (1.f / 128.f);
        float var = ts2 * (1.f / 128.f) - mu * mu;
        sMu[tid] = mu;
        sRs[tid] = rsqrtf(var + 1e-5f);
    }
    __syncthreads();

    #pragma unroll
    for (int mi = 0; mi < 2; ++mi)
        #pragma unroll
        for (int h = 0; h < 2; ++h) {
            int R = 32 * wr + 16 * mi + 8 * h + g;
            float mu = sMu[R], rs = sRs[R];
            #pragma unroll
            for (int nj = 0; nj < 8; ++nj) {
                int C = 64 * wc + 8 * nj + 2 * q;
                float v0 = fmaxf((acc[mi][nj][2 * h] - mu) * rs * __ldg(&gamma[C]) + __ldg(&beta[C]), 0.f);
                float v1 = fmaxf((acc[mi][nj][2 * h + 1] - mu) * rs * __ldg(&gamma[C + 1]) + __ldg(&beta[C + 1]), 0.f);
                if constexpr (sizeof(OutT) == 2)
                    *(__half2*)((__half*)ob + (size_t)R * HID + C) = __floats2half2_rn(v0, v1);
                else
                    *(float2*)((float*)ob + (size_t)R * HID + C) = make_float2(v0, v1);
            }
        }
}

// ---------------------------------------------------------------------------
// conv_w: converts the three 128x128 weight matrices in one launch.
// ---------------------------------------------------------------------------
__global__ __launch_bounds__(256) void conv_w(const float* __restrict__ W0,
                                              const float* __restrict__ W1,
                                              const float* __restrict__ W2,
                                              __half* __restrict__ out)
{
    int i = blockIdx.x * blockDim.x + threadIdx.x;           // 0 .. 3*16384-1
    const float* src = (i < 16384) ? W0 : (i < 32768) ? W1 : W2;
    int off = i & 16383;
    out[i] = __float2half_rn(src[off]);
}

// ---------------------------------------------------------------------------
// pw_half<InT>: p[r, :] = fp16( src[r, :] @ W )   manual m16n8k16, K=128.
// 128-row tiles, 2 CTAs/SM (R14 shape — the 64-row variant regressed).
// InT = __half: cp.async A load. InT = float: LDG fp32 -> cvt -> STS fp16
// (layer 0 consumes x directly; no separate x conversion pass).
// ---------------------------------------------------------------------------
#define PW_LD   136
#define PW_SMEM (2 * 128 * PW_LD * 2)       // 69632 B

template<typename InT>
__global__ __launch_bounds__(256, 2) void pw_half(const InT* __restrict__ src,
                                                  const __half* __restrict__ W,
                                                  __half* __restrict__ out)
{
    extern __shared__ char smraw[];
    __half* sA = (__half*)smraw;
    __half* sB = sA + 128 * PW_LD;

    const int tid  = threadIdx.x;
    const int warp = tid >> 5;
    const int lane = tid & 31;
    const int wr   = warp >> 1;
    const int wc   = warp & 1;
    const size_t row0 = (size_t)blockIdx.x * 128;

    // B (weights) always via cp.async
    #pragma unroll
    for (int it = 0; it < 8; ++it) {
        int i = tid + it * 256;
        int r = i >> 4, c = i & 15;
        cp_async16(sB + r * PW_LD + c * 8, W + r * HID + c * 8);
    }

    if constexpr (sizeof(InT) == 2) {
        #pragma unroll
        for (int it = 0; it < 8; ++it) {
            int i = tid + it * 256;
            int r = i >> 4, c = i & 15;
            cp_async16(sA + r * PW_LD + c * 8, (const __half*)src + (row0 + r) * HID + c * 8);
        }
        cp_commit();
        cp_wait<0>();
    } else {
        cp_commit();
        // fp32 input: LDG float4 pairs -> convert -> STS 16B fp16 chunks
        #pragma unroll
        for (int it = 0; it < 8; ++it) {
            int i = tid + it * 256;
            int r = i >> 4, c = i & 15;   // c = 8-half group
            const float* s0 = (const float*)src + (row0 + r) * HID + c * 8;
            float4 v0 = *(const float4*)(s0);
            float4 v1 = *(const float4*)(s0 + 4);
            union { __half2 h[4]; uint4 u; } pk;
            pk.h[0] = __floats2half2_rn(v0.x, v0.y);
            pk.h[1] = __floats2half2_rn(v0.z, v0.w);
            pk.h[2] = __floats2half2_rn(v1.x, v1.y);
            pk.h[3] = __floats2half2_rn(v1.z, v1.w);
            *(uint4*)(sA + r * PW_LD + c * 8) = pk.u;
        }
        cp_wait<0>();
    }
    __syncthreads();

    float acc[2][8][4] = {};
    mma_steps<PW_LD, 8>(acc, sptr(sA), sptr(sB), wr, wc, lane);

    // store epilogue straight from registers (no LN for pw)
    const int g = lane >> 2, q = lane & 3;
    __half* ob = out + row0 * HID;
    #pragma unroll
    for (int mi = 0; mi < 2; ++mi)
        #pragma unroll
        for (int h = 0; h < 2; ++h) {
            int R = 32 * wr + 16 * mi + 8 * h + g;
            #pragma unroll
            for (int nj = 0; nj < 8; ++nj) {
                int C = 64 * wc + 8 * nj + 2 * q;
                *(__half2*)(ob + (size_t)R * HID + C) =
                    __floats2half2_rn(acc[mi][nj][2 * h], acc[mi][nj][2 * h + 1]);
            }
        }
}

// ---------------------------------------------------------------------------
// agg_half (layers 1,2): C = adjh @ p, manual mma, KC=64, 3-stage cp.async,
// fused +bias / LN / ReLU register epilogue.  (unchanged from R14)
// ---------------------------------------------------------------------------
#define KC     64
#define A_LDH  72
#define A_STGB (128 * A_LDH * 2)            // 18432 B
#define B_STGB (KC * B_LDH * 2)             // 17408 B
#define OFF_B  (3 * A_STGB)                 // 55296
#define AGG_SMEM (OFF_B + 3 * B_STGB)       // 107520 B

__device__ __forceinline__ void agg_load_stage(char* smem, int stg,
                                               const __half* __restrict__ adjb,
                                               const __half* __restrict__ pb,
                                               int k0, int tid)
{
    char* sA = smem + stg * A_STGB;
    char* sB = smem + OFF_B + stg * B_STGB;
    #pragma unroll
    for (int it = 0; it < 4; ++it) {
        int i = tid + it * 256;
        int r = i >> 3, c = i & 7;
        cp_async16(sA + (r * A_LDH + c * 8) * 2,
                   adjb + (size_t)r * N_SZ + k0 + c * 8);
    }
    #pragma unroll
    for (int it = 0; it < 4; ++it) {
        int i = tid + it * 256;
        int r = i >> 4, c = i & 15;
        cp_async16(sB + (r * B_LDH + c * 8) * 2,
                   pb + (size_t)(k0 + r) * HID + c * 8);
    }
    cp_commit();
}

template<typename OutT>
__global__ __launch_bounds__(256, 2) void agg_half(const __half* __restrict__ adjh,
                                                   const __half* __restrict__ p,
                                                   const float* __restrict__ bias,
                                                   const float* __restrict__ gamma,
                                                   const float* __restrict__ beta,
                                                   OutT* __restrict__ out)
{
    extern __shared__ char smem[];

    const int tid  = threadIdx.x;
    const int warp = tid >> 5;
    const int lane = tid & 31;
    const int wr   = warp >> 1;
    const int wc   = warp & 1;
    const int b    = blockIdx.y;
    const int n0   = blockIdx.x * 128;

    const __half* adjb = adjh + ((size_t)b * N_SZ + n0) * N_SZ;
    const __half* pb   = p + (size_t)b * N_SZ * HID;

    float acc[2][8][4] = {};

    agg_load_stage(smem, 0, adjb, pb, 0, tid);
    agg_load_stage(smem, 1, adjb, pb, KC, tid);

    const unsigned smemBase = sptr(smem);
    const int NT = N_SZ / KC;   // 32
    for (int kt = 0; kt < NT; ++kt) {
        cp_wait<1>();
        __syncthreads();

        int nk = kt + 2;
        if (nk < NT) agg_load_stage(smem, nk % 3, adjb, pb, nk * KC, tid);
        else         cp_commit();

        const int stg = kt % 3;
        mma_steps<A_LDH, KC / 16>(acc,
                                  smemBase + stg * A_STGB,
                                  smemBase + OFF_B + stg * B_STGB,
                                  wr, wc, lane);
    }
    __syncthreads();   // stage reads done; smem reusable for LN stats

    OutT* ob = out + ((size_t)b * N_SZ + n0) * HID;
    ln_epilogue<OutT>(acc, smem, bias, gamma, beta, ob, wr, wc, lane, tid);
}

// ---------------------------------------------------------------------------
// agg_conv (layer 0): cp.async fp32 adj staging (3 stages, KC=32), single
// sync per iteration: convert(stage kt -> A16[kt%2], + STG.128 to g_adjh)
// overlaps MMA on A16[(kt-1)%2] x B[(kt-1)%4]. Register LN epilogue.
// (R14 version.)
// ---------------------------------------------------------------------------
#define CKC       32
#define CV_A32LD  36                          // floats per fp32 A row (32+4)
#define CV_A32B   (128 * CV_A32LD * 4)        // 18432 B
#define CV_A16LD  40                          // halfs per fp16 A row (32+8)
#define CV_A16B   (128 * CV_A16LD * 2)        // 10240 B
#define CV_OFF_A16 (3 * CV_A32B)              // 55296
#define CV_BSTG   (CKC * B_LDH * 2)           // 8704 B
#define CV_OFF_B  (CV_OFF_A16 + 2 * CV_A16B)  // 75776
#define CONV_SMEM (CV_OFF_B + 4 * CV_BSTG)    // 110592 B

__device__ __forceinline__ void conv_load_stage(char* smem, int a_stg, int b_stg,
                                                const float* __restrict__ adjb,
                                                const __half* __restrict__ pb,
                                                int k0, int tid)
{
    float* sA = (float*)(smem + a_stg * CV_A32B);
    char*  sB = smem + CV_OFF_B + b_stg * CV_BSTG;
    #pragma unroll
    for (int it = 0; it < 4; ++it) {          // 1024 chunks: 128 rows x 8 float4
        int i = tid + it * 256;
        int r = i >> 3, c = i & 7;
        cp_async16(sA + r * CV_A32LD + c * 4,
                   adjb + (size_t)r * N_SZ + k0 + c * 4);
    }
    #pragma unroll
    for (int it = 0; it < 2; ++it) {          // 512 chunks: 32 rows x 16
        int i = tid + it * 256;
        int r = i >> 4, c = i & 15;
        cp_async16(sB + (r * B_LDH + c * 8) * 2,
                   pb + (size_t)(k0 + r) * HID + c * 8);
    }
    cp_commit();
}

__global__ __launch_bounds__(256, 2) void agg_conv(const float* __restrict__ adj,
                                                   const __half* __restrict__ p,
                                                   const float* __restrict__ bias,
                                                   const float* __restrict__ gamma,
                                                   const float* __restrict__ beta,
                                                   __half* __restrict__ adjh_out,
                                                   __half* __restrict__ out)
{
    extern __shared__ char smem[];

    const int tid  = threadIdx.x;
    const int warp = tid >> 5;
    const int lane = tid & 31;
    const int wr   = warp >> 1;
    const int wc   = warp & 1;
    const int b    = blockIdx.y;
    const int n0   = blockIdx.x * 128;

    const float*  adjb  = adj + ((size_t)b * N_SZ + n0) * N_SZ;
    __half*       adjhb = adjh_out + ((size_t)b * N_SZ + n0) * N_SZ;
    const __half* pb    = p + (size_t)b * N_SZ * HID;

    float acc[2][8][4] = {};

    // prologue: two stages in flight
    conv_load_stage(smem, 0, 0, adjb, pb, 0, tid);
    conv_load_stage(smem, 1, 1, adjb, pb, CKC, tid);

    const unsigned smemBase = sptr(smem);
    const int NT = N_SZ / CKC;   // 64
    for (int kt = 0; kt < NT; ++kt) {
        cp_wait<1>();
        __syncthreads();          // fp32 stage kt + B stage kt ready;
                                  // also: A16[(kt-1)%2] writes visible

        int nk = kt + 2;
        if (nk < NT) conv_load_stage(smem, nk % 3, nk % 4, adjb, pb, nk * CKC, tid);
        else         cp_commit();

        // convert fp32 stage kt -> A16[kt%2] (+ fp16 adjacency to gmem)
        {
            const float* a32 = (const float*)(smem + (kt % 3) * CV_A32B);
            __half* a16 = (__half*)(smem + CV_OFF_A16 + (kt & 1) * CV_A16B);
            const int k0 = kt * CKC;
            #pragma unroll
            for (int it = 0; it < 2; ++it) {   // 512 out-chunks of 16B
                int i = tid + it * 256;
                int r = i >> 2, j = i & 3;     // 128 rows x 4 groups of 8 floats
                float4 v0 = *(const float4*)(a32 + r * CV_A32LD + j * 8);
                float4 v1 = *(const float4*)(a32 + r * CV_A32LD + j * 8 + 4);
                union { __half2 h[4]; uint4 u; } pk;
                pk.h[0] = __floats2half2_rn(v0.x, v0.y);
                pk.h[1] = __floats2half2_rn(v0.z, v0.w);
                pk.h[2] = __floats2half2_rn(v1.x, v1.y);
                pk.h[3] = __floats2half2_rn(v1.z, v1.w);
                *(uint4*)(a16 + r * CV_A16LD + j * 8) = pk.u;
                *(uint4*)(adjhb + (size_t)r * N_SZ + k0 + j * 8) = pk.u;
            }
        }

        // MMA lags by one k-chunk: consumes A16[(kt-1)%2] x B[(kt-1)%4]
        if (kt > 0) {
            mma_steps<CV_A16LD, CKC / 16>(acc,
                smemBase + CV_OFF_A16 + ((kt - 1) & 1) * CV_A16B,
                smemBase + CV_OFF_B + ((kt - 1) & 3) * CV_BSTG,
                wr, wc, lane);
        }
    }

    // tail: final k-chunk's MMA
    __syncthreads();   // last convert visible to all warps
    mma_steps<CV_A16LD, CKC / 16>(acc,
        smemBase + CV_OFF_A16 + ((NT - 1) & 1) * CV_A16B,
        smemBase + CV_OFF_B + ((NT - 1) & 3) * CV_BSTG,
        wr, wc, lane);
    __syncthreads();   // all reads done; smem reusable for LN stats

    __half* ob = out + ((size_t)b * N_SZ + n0) * HID;
    ln_epilogue<__half>(acc, smem, bias, gamma, beta, ob, wr, wc, lane, tid);
}

// ---------------------------------------------------------------------------
extern "C" void kernel_launch(void* const* d_in, const int* in_sizes, int n_in,
                              void* d_out, int out_size)
{
    const float* x   = (const float*)d_in[0];
    const float* adj = (const float*)d_in[1];
    const float* W[3]  = {(const float*)d_in[2],  (const float*)d_in[6],  (const float*)d_in[10]};
    const float* bb[3] = {(const float*)d_in[3],  (const float*)d_in[7],  (const float*)d_in[11]};
    const float* gg[3] = {(const float*)d_in[4],  (const float*)d_in[8],  (const float*)d_in[12]};
    const float* be[3] = {(const float*)d_in[5],  (const float*)d_in[9],  (const float*)d_in[13]};
    float* out = (float*)d_out;

    cudaFuncSetAttribute(pw_half<float>,  cudaFuncAttributeMaxDynamicSharedMemorySize, PW_SMEM);
    cudaFuncSetAttribute(pw_half<__half>, cudaFuncAttributeMaxDynamicSharedMemorySize, PW_SMEM);
    cudaFuncSetAttribute(agg_half<__half>, cudaFuncAttributeMaxDynamicSharedMemorySize, AGG_SMEM);
    cudaFuncSetAttribute(agg_half<float>,  cudaFuncAttributeMaxDynamicSharedMemorySize, AGG_SMEM);
    cudaFuncSetAttribute(agg_conv, cudaFuncAttributeMaxDynamicSharedMemorySize, CONV_SMEM);

    __half *adjh, *pp, *hh, *wh;
    cudaGetSymbolAddress((void**)&adjh, g_adjh);
    cudaGetSymbolAddress((void**)&pp,   g_p);
    cudaGetSymbolAddress((void**)&hh,   g_hh);
    cudaGetSymbolAddress((void**)&wh,   g_wh);

    // convert the three weight matrices (tiny)
    conv_w<<<192, 256>>>(W[0], W[1], W[2], wh);

    dim3 aggGrid(N_SZ / 128, B_SZ);   // (16, 16)
    const int pwGrid = (B_SZ * N_SZ) / 128;   // 256

    // layer 0: projection straight from fp32 x, then fused convert+agg
    pw_half<float><<<pwGrid, 256, PW_SMEM>>>(x, wh, pp);
    agg_conv<<<aggGrid, 256, CONV_SMEM>>>(adj, pp, bb[0], gg[0], be[0], adjh, hh);
    // layer 1
    pw_half<__half><<<pwGrid, 256, PW_SMEM>>>(hh, wh + 1 * HID * HID, pp);
    agg_half<__half><<<aggGrid, 256, AGG_SMEM>>>(adjh, pp, bb[1], gg[1], be[1], hh);
    // layer 2
    pw_half<__half><<<pwGrid, 256, PW_SMEM>>>(hh, wh + 2 * HID * HID, pp);
    agg_half<float><<<aggGrid, 256, AGG_SMEM>>>(adjh, pp, bb[2], gg[2], be[2], out);
}